// round 3
// baseline (speedup 1.0000x reference)
#include <cuda_runtime.h>

// MyModel_83597243450144 : 4-layer LSTM autoencoder, fp32 SIMT implementation.
// B=2048, T=128, H1=128, H2=64. Gate order i,f,g,o; g uses relu, h = o*relu(c).
//
// Phase A: layers 1+2 fused per timestep; writes h2[t=127] to g_h2last.
// Phase B: layers 3+4+dense fused per timestep; layer3 input path precomputed.

#define B_ALL 2048
#define T_SEQ 128
#define BT 16
#define NBLK (B_ALL / BT)  // 128 CTAs
#define HROW 20            // padded shared row stride (floats) for hcat

// ---- device scratch (no allocations allowed) ----
__device__ float g_U1p[128 * 512];   // [k][u*4+g]  (U1 repacked)
__device__ float g_WU2p[192 * 256];  // k<128: W2, k>=128: U2
__device__ float g_W3p[64 * 256];
__device__ float g_U3p[64 * 256];
__device__ float g_WU4p[192 * 512];  // k<64: W4, k>=64: U4
__device__ float g_h2last[B_ALL * 64];

__device__ __forceinline__ float sigmoidf_(float v) {
    return __fdividef(1.0f, 1.0f + __expf(-v));
}

// ---------------------------------------------------------------------------
// Weight repack: per hidden unit u, the 4 gate weights (i,f,g,o) become one
// contiguous float4 so the inner loop does a single coalesced LDG.128.
// Total elements = 65536 + 49152 + 16384 + 16384 + 98304 = 245760 = 960*256.
// ---------------------------------------------------------------------------
__global__ void pack_kernel(const float* __restrict__ U1,
                            const float* __restrict__ W2, const float* __restrict__ U2,
                            const float* __restrict__ W3, const float* __restrict__ U3,
                            const float* __restrict__ W4, const float* __restrict__ U4) {
    int e = blockIdx.x * blockDim.x + threadIdx.x;
    if (e < 65536) {  // U1p: [128][512]
        int k = e >> 9, r = e & 511, u = r >> 2, g = r & 3;
        g_U1p[e] = U1[k * 512 + g * 128 + u];
        return;
    }
    int e2 = e - 65536;
    if (e2 < 49152) {  // WU2p: [192][256]
        int k = e2 >> 8, r = e2 & 255, u = r >> 2, g = r & 3;
        g_WU2p[e2] = (k < 128) ? W2[k * 256 + g * 64 + u]
                               : U2[(k - 128) * 256 + g * 64 + u];
        return;
    }
    int e3 = e2 - 49152;
    if (e3 < 16384) {  // W3p: [64][256]
        int k = e3 >> 8, r = e3 & 255, u = r >> 2, g = r & 3;
        g_W3p[e3] = W3[k * 256 + g * 64 + u];
        return;
    }
    int e4 = e3 - 16384;
    if (e4 < 16384) {  // U3p: [64][256]
        int k = e4 >> 8, r = e4 & 255, u = r >> 2, g = r & 3;
        g_U3p[e4] = U3[k * 256 + g * 64 + u];
        return;
    }
    int e5 = e4 - 16384;
    if (e5 < 98304) {  // WU4p: [192][512]
        int k = e5 >> 9, r = e5 & 511, u = r >> 2, g = r & 3;
        g_WU4p[e5] = (k < 64) ? W4[k * 512 + g * 128 + u]
                              : U4[(k - 64) * 512 + g * 128 + u];
    }
}

// ---------------------------------------------------------------------------
// Phase A: LSTM1 (H=128) + LSTM2 (H=64), 16 samples per CTA.
// hcat rows 0..127 = h1 (k-major [k][b]), rows 128..191 = h2. Stride HROW=20.
// ---------------------------------------------------------------------------
__global__ void __launch_bounds__(256, 1)
phaseA_kernel(const float* __restrict__ x, const float* __restrict__ W1,
              const float* __restrict__ b1, const float* __restrict__ b2) {
    __shared__ float hcat[192 * HROW];
    __shared__ float xs[T_SEQ * BT];

    const int tid = threadIdx.x;
    const int b0 = blockIdx.x * BT;

    // stage x tile [16][128] -> xs[t][b]
    for (int i = tid; i < T_SEQ * BT; i += 256) {
        int b = i >> 7, t = i & 127;
        xs[t * BT + b] = x[(b0 + b) * T_SEQ + t];
    }
    for (int i = tid; i < 192 * HROW; i += 256) hcat[i] = 0.0f;

    // layer-1 map: unit u1 in [0,128), 8 samples; layer-2 map: u2 in [0,64), 4 samples
    const int u1 = tid & 127, bg1 = tid >> 7;
    const int u2 = tid & 63,  bg2 = tid >> 6;

    const float4* __restrict__ U1p4  = (const float4*)g_U1p;   // [k*128 + u1]
    const float4* __restrict__ WU2p4 = (const float4*)g_WU2p;  // [k*64  + u2]

    const float4 w1q = make_float4(W1[u1], W1[128 + u1], W1[256 + u1], W1[384 + u1]);
    const float4 b1q = make_float4(b1[u1], b1[128 + u1], b1[256 + u1], b1[384 + u1]);
    const float4 b2q = make_float4(b2[u2], b2[64 + u2], b2[128 + u2], b2[192 + u2]);

    float c1[8], c2[4];
#pragma unroll
    for (int j = 0; j < 8; j++) c1[j] = 0.0f;
#pragma unroll
    for (int j = 0; j < 4; j++) c2[j] = 0.0f;

    __syncthreads();

    for (int t = 0; t < T_SEQ; t++) {
        // ---- layer 1: z1 = x_t*W1 + h1 @ U1 + b1 ----
        float ai[8], af[8], ag[8], ao[8];
#pragma unroll
        for (int j = 0; j < 8; j++) {
            float xv = xs[t * BT + bg1 * 8 + j];
            ai[j] = fmaf(xv, w1q.x, b1q.x);
            af[j] = fmaf(xv, w1q.y, b1q.y);
            ag[j] = fmaf(xv, w1q.z, b1q.z);
            ao[j] = fmaf(xv, w1q.w, b1q.w);
        }
        const float* hp = hcat + bg1 * 8;
#pragma unroll 4
        for (int k = 0; k < 128; k++) {
            float4 w  = U1p4[k * 128 + u1];
            float4 hA = *(const float4*)(hp + k * HROW);
            float4 hB = *(const float4*)(hp + k * HROW + 4);
            float hv[8] = {hA.x, hA.y, hA.z, hA.w, hB.x, hB.y, hB.z, hB.w};
#pragma unroll
            for (int j = 0; j < 8; j++) {
                ai[j] = fmaf(hv[j], w.x, ai[j]);
                af[j] = fmaf(hv[j], w.y, af[j]);
                ag[j] = fmaf(hv[j], w.z, ag[j]);
                ao[j] = fmaf(hv[j], w.w, ao[j]);
            }
        }
        __syncthreads();  // all reads of old h1 complete
#pragma unroll
        for (int j = 0; j < 8; j++) {
            float iv = sigmoidf_(ai[j]);
            float fv = sigmoidf_(af[j]);
            float gv = fmaxf(ag[j], 0.0f);
            float ov = sigmoidf_(ao[j]);
            float c  = fmaf(fv, c1[j], iv * gv);
            c1[j] = c;
            hcat[u1 * HROW + bg1 * 8 + j] = ov * fmaxf(c, 0.0f);
        }
        __syncthreads();  // new h1 visible

        // ---- layer 2: z2 = h1_t @ W2 + h2 @ U2 + b2 (single K=192 loop) ----
        float a2i[4], a2f[4], a2g[4], a2o[4];
#pragma unroll
        for (int j = 0; j < 4; j++) {
            a2i[j] = b2q.x; a2f[j] = b2q.y; a2g[j] = b2q.z; a2o[j] = b2q.w;
        }
        const float* hp2 = hcat + bg2 * 4;
#pragma unroll 4
        for (int k = 0; k < 192; k++) {
            float4 w = WU2p4[k * 64 + u2];
            float4 h = *(const float4*)(hp2 + k * HROW);
            float hv[4] = {h.x, h.y, h.z, h.w};
#pragma unroll
            for (int j = 0; j < 4; j++) {
                a2i[j] = fmaf(hv[j], w.x, a2i[j]);
                a2f[j] = fmaf(hv[j], w.y, a2f[j]);
                a2g[j] = fmaf(hv[j], w.z, a2g[j]);
                a2o[j] = fmaf(hv[j], w.w, a2o[j]);
            }
        }
        __syncthreads();  // all reads of old h2 complete
#pragma unroll
        for (int j = 0; j < 4; j++) {
            float iv = sigmoidf_(a2i[j]);
            float fv = sigmoidf_(a2f[j]);
            float gv = fmaxf(a2g[j], 0.0f);
            float ov = sigmoidf_(a2o[j]);
            float c  = fmaf(fv, c2[j], iv * gv);
            c2[j] = c;
            float h = ov * fmaxf(c, 0.0f);
            hcat[(128 + u2) * HROW + bg2 * 4 + j] = h;
            if (t == T_SEQ - 1) g_h2last[(b0 + bg2 * 4 + j) * 64 + u2] = h;
        }
        // next-iteration layer-1 pass only touches rows <128; the two barriers
        // above separate this write from the next read of rows >=128.
    }
}

// ---------------------------------------------------------------------------
// Phase B: RepeatVector(h2_last) -> LSTM3 (H=64) -> LSTM4 (H=128) -> Dense(1).
// hcat rows 0..63 = h3, rows 64..191 = h4.
// Layer-3 input path (h2_last @ W3 + b3) is constant over t -> held in regs.
// ---------------------------------------------------------------------------
__global__ void __launch_bounds__(256, 1)
phaseB_kernel(const float* __restrict__ b3, const float* __restrict__ b4,
              const float* __restrict__ Wd, const float* __restrict__ bd,
              float* __restrict__ out) {
    __shared__ float hcat[192 * HROW];
    __shared__ float h2T[64 * BT];  // [k][b]

    const int tid = threadIdx.x;
    const int b0 = blockIdx.x * BT;

    for (int i = tid; i < 64 * BT; i += 256) {
        int b = i >> 6, k = i & 63;
        h2T[k * BT + b] = g_h2last[(b0 + b) * 64 + k];
    }
    for (int i = tid; i < 192 * HROW; i += 256) hcat[i] = 0.0f;

    const int u3 = tid & 63,  bg  = tid >> 6;  // 4 samples
    const int u4 = tid & 127, bg2 = tid >> 7;  // 8 samples
    const int lane16 = tid & 15, bq = tid >> 4;

    const float4* __restrict__ W3p4  = (const float4*)g_W3p;
    const float4* __restrict__ U3p4  = (const float4*)g_U3p;
    const float4* __restrict__ WU4p4 = (const float4*)g_WU4p;

    const float4 b4q = make_float4(b4[u4], b4[128 + u4], b4[256 + u4], b4[384 + u4]);
    float wd[8];
#pragma unroll
    for (int r = 0; r < 8; r++) wd[r] = Wd[lane16 + 16 * r];
    const float bdv = bd[0];

    __syncthreads();

    // precompute zx3 = h2_last @ W3 + b3 (constant over t) into registers
    float zi[4], zf[4], zg[4], zo[4];
    {
        const float4 b3q = make_float4(b3[u3], b3[64 + u3], b3[128 + u3], b3[192 + u3]);
#pragma unroll
        for (int j = 0; j < 4; j++) { zi[j] = b3q.x; zf[j] = b3q.y; zg[j] = b3q.z; zo[j] = b3q.w; }
#pragma unroll 4
        for (int k = 0; k < 64; k++) {
            float4 w = W3p4[k * 64 + u3];
            float4 h = *(const float4*)(h2T + k * BT + bg * 4);
            float hv[4] = {h.x, h.y, h.z, h.w};
#pragma unroll
            for (int j = 0; j < 4; j++) {
                zi[j] = fmaf(hv[j], w.x, zi[j]);
                zf[j] = fmaf(hv[j], w.y, zf[j]);
                zg[j] = fmaf(hv[j], w.z, zg[j]);
                zo[j] = fmaf(hv[j], w.w, zo[j]);
            }
        }
    }

    float c3[4], c4[8];
#pragma unroll
    for (int j = 0; j < 4; j++) c3[j] = 0.0f;
#pragma unroll
    for (int j = 0; j < 8; j++) c4[j] = 0.0f;

    for (int t = 0; t < T_SEQ; t++) {
        // ---- layer 3: z3 = zx3 + h3 @ U3 ----
        float a3i[4], a3f[4], a3g[4], a3o[4];
#pragma unroll
        for (int j = 0; j < 4; j++) { a3i[j] = zi[j]; a3f[j] = zf[j]; a3g[j] = zg[j]; a3o[j] = zo[j]; }
        const float* hp3 = hcat + bg * 4;
#pragma unroll 4
        for (int k = 0; k < 64; k++) {
            float4 w = U3p4[k * 64 + u3];
            float4 h = *(const float4*)(hp3 + k * HROW);
            float hv[4] = {h.x, h.y, h.z, h.w};
#pragma unroll
            for (int j = 0; j < 4; j++) {
                a3i[j] = fmaf(hv[j], w.x, a3i[j]);
                a3f[j] = fmaf(hv[j], w.y, a3f[j]);
                a3g[j] = fmaf(hv[j], w.z, a3g[j]);
                a3o[j] = fmaf(hv[j], w.w, a3o[j]);
            }
        }
        __syncthreads();
#pragma unroll
        for (int j = 0; j < 4; j++) {
            float iv = sigmoidf_(a3i[j]);
            float fv = sigmoidf_(a3f[j]);
            float gv = fmaxf(a3g[j], 0.0f);
            float ov = sigmoidf_(a3o[j]);
            float c  = fmaf(fv, c3[j], iv * gv);
            c3[j] = c;
            hcat[u3 * HROW + bg * 4 + j] = ov * fmaxf(c, 0.0f);
        }
        __syncthreads();

        // ---- layer 4: z4 = h3_t @ W4 + h4 @ U4 + b4 (K=192) ----
        float a4i[8], a4f[8], a4g[8], a4o[8];
#pragma unroll
        for (int j = 0; j < 8; j++) { a4i[j] = b4q.x; a4f[j] = b4q.y; a4g[j] = b4q.z; a4o[j] = b4q.w; }
        const float* hp4 = hcat + bg2 * 8;
#pragma unroll 4
        for (int k = 0; k < 192; k++) {
            float4 w  = WU4p4[k * 128 + u4];
            float4 hA = *(const float4*)(hp4 + k * HROW);
            float4 hB = *(const float4*)(hp4 + k * HROW + 4);
            float hv[8] = {hA.x, hA.y, hA.z, hA.w, hB.x, hB.y, hB.z, hB.w};
#pragma unroll
            for (int j = 0; j < 8; j++) {
                a4i[j] = fmaf(hv[j], w.x, a4i[j]);
                a4f[j] = fmaf(hv[j], w.y, a4f[j]);
                a4g[j] = fmaf(hv[j], w.z, a4g[j]);
                a4o[j] = fmaf(hv[j], w.w, a4o[j]);
            }
        }
        __syncthreads();
#pragma unroll
        for (int j = 0; j < 8; j++) {
            float iv = sigmoidf_(a4i[j]);
            float fv = sigmoidf_(a4f[j]);
            float gv = fmaxf(a4g[j], 0.0f);
            float ov = sigmoidf_(a4o[j]);
            float c  = fmaf(fv, c4[j], iv * gv);
            c4[j] = c;
            hcat[(64 + u4) * HROW + bg2 * 8 + j] = ov * fmaxf(c, 0.0f);
        }
        __syncthreads();

        // ---- dense: out[b][t] = h4 . Wd + bd (16-lane tree per sample) ----
        float s = 0.0f;
#pragma unroll
        for (int r = 0; r < 8; r++)
            s = fmaf(hcat[(64 + lane16 + 16 * r) * HROW + bq], wd[r], s);
        s += __shfl_xor_sync(0xffffffffu, s, 8);
        s += __shfl_xor_sync(0xffffffffu, s, 4);
        s += __shfl_xor_sync(0xffffffffu, s, 2);
        s += __shfl_xor_sync(0xffffffffu, s, 1);
        if (lane16 == 0) out[(b0 + bq) * T_SEQ + t] = s + bdv;
        // dense reads complete before bar1 of the next iteration; h4 rows are
        // rewritten only after three more barriers.
    }
}

// ---------------------------------------------------------------------------
extern "C" void kernel_launch(void* const* d_in, const int* in_sizes, int n_in,
                              void* d_out, int out_size) {
    const float* x  = (const float*)d_in[0];
    const float* W1 = (const float*)d_in[1];
    const float* U1 = (const float*)d_in[2];
    const float* b1 = (const float*)d_in[3];
    const float* W2 = (const float*)d_in[4];
    const float* U2 = (const float*)d_in[5];
    const float* b2 = (const float*)d_in[6];
    const float* W3 = (const float*)d_in[7];
    const float* U3 = (const float*)d_in[8];
    const float* b3 = (const float*)d_in[9];
    const float* W4 = (const float*)d_in[10];
    const float* U4 = (const float*)d_in[11];
    const float* b4 = (const float*)d_in[12];
    const float* Wd = (const float*)d_in[13];
    const float* bd = (const float*)d_in[14];
    float* out = (float*)d_out;

    pack_kernel<<<960, 256>>>(U1, W2, U2, W3, U3, W4, U4);
    phaseA_kernel<<<NBLK, 256>>>(x, W1, b1, b2);
    phaseB_kernel<<<NBLK, 256>>>(b3, b4, Wd, bd, out);
}

// round 4
// speedup vs baseline: 1.0003x; 1.0003x over previous
#include <cuda_runtime.h>

// MyModel_83597243450144 : 4-layer LSTM autoencoder, fp32 SIMT implementation.
// B=2048, T=128, H1=128, H2=64. Gate order i,f,g,o; g uses relu, h = o*relu(c).
//
// Phase A: layers 1+2 fused per timestep; writes h2[t=127] to g_h2last.
// Phase B: layers 3+4+dense fused per timestep; layer3 input path precomputed.

#define B_ALL 2048
#define T_SEQ 128
#define BT 16
#define NBLK (B_ALL / BT)  // 128 CTAs
#define HROW 20            // padded shared row stride (floats) for hcat

// ---- device scratch (no allocations allowed) ----
__device__ float g_U1p[128 * 512];   // [k][u*4+g]  (U1 repacked)
__device__ float g_WU2p[192 * 256];  // k<128: W2, k>=128: U2
__device__ float g_W3p[64 * 256];
__device__ float g_U3p[64 * 256];
__device__ float g_WU4p[192 * 512];  // k<64: W4, k>=64: U4
__device__ float g_h2last[B_ALL * 64];

__device__ __forceinline__ float sigmoidf_(float v) {
    return __fdividef(1.0f, 1.0f + __expf(-v));
}

// ---------------------------------------------------------------------------
// Weight repack: per hidden unit u, the 4 gate weights (i,f,g,o) become one
// contiguous float4 so the inner loop does a single coalesced LDG.128.
// Total elements = 65536 + 49152 + 16384 + 16384 + 98304 = 245760 = 960*256.
// ---------------------------------------------------------------------------
__global__ void pack_kernel(const float* __restrict__ U1,
                            const float* __restrict__ W2, const float* __restrict__ U2,
                            const float* __restrict__ W3, const float* __restrict__ U3,
                            const float* __restrict__ W4, const float* __restrict__ U4) {
    int e = blockIdx.x * blockDim.x + threadIdx.x;
    if (e < 65536) {  // U1p: [128][512]
        int k = e >> 9, r = e & 511, u = r >> 2, g = r & 3;
        g_U1p[e] = U1[k * 512 + g * 128 + u];
        return;
    }
    int e2 = e - 65536;
    if (e2 < 49152) {  // WU2p: [192][256]
        int k = e2 >> 8, r = e2 & 255, u = r >> 2, g = r & 3;
        g_WU2p[e2] = (k < 128) ? W2[k * 256 + g * 64 + u]
                               : U2[(k - 128) * 256 + g * 64 + u];
        return;
    }
    int e3 = e2 - 49152;
    if (e3 < 16384) {  // W3p: [64][256]
        int k = e3 >> 8, r = e3 & 255, u = r >> 2, g = r & 3;
        g_W3p[e3] = W3[k * 256 + g * 64 + u];
        return;
    }
    int e4 = e3 - 16384;
    if (e4 < 16384) {  // U3p: [64][256]
        int k = e4 >> 8, r = e4 & 255, u = r >> 2, g = r & 3;
        g_U3p[e4] = U3[k * 256 + g * 64 + u];
        return;
    }
    int e5 = e4 - 16384;
    if (e5 < 98304) {  // WU4p: [192][512]
        int k = e5 >> 9, r = e5 & 511, u = r >> 2, g = r & 3;
        g_WU4p[e5] = (k < 64) ? W4[k * 512 + g * 128 + u]
                              : U4[(k - 64) * 512 + g * 128 + u];
    }
}

// ---------------------------------------------------------------------------
// Phase A: LSTM1 (H=128) + LSTM2 (H=64), 16 samples per CTA.
// hcat rows 0..127 = h1 (k-major [k][b]), rows 128..191 = h2. Stride HROW=20.
// ---------------------------------------------------------------------------
__global__ void __launch_bounds__(256, 1)
phaseA_kernel(const float* __restrict__ x, const float* __restrict__ W1,
              const float* __restrict__ b1, const float* __restrict__ b2) {
    __shared__ float hcat[192 * HROW];
    __shared__ float xs[T_SEQ * BT];

    const int tid = threadIdx.x;
    const int b0 = blockIdx.x * BT;

    // stage x tile [16][128] -> xs[t][b]
    for (int i = tid; i < T_SEQ * BT; i += 256) {
        int b = i >> 7, t = i & 127;
        xs[t * BT + b] = x[(b0 + b) * T_SEQ + t];
    }
    for (int i = tid; i < 192 * HROW; i += 256) hcat[i] = 0.0f;

    // layer-1 map: unit u1 in [0,128), 8 samples; layer-2 map: u2 in [0,64), 4 samples
    const int u1 = tid & 127, bg1 = tid >> 7;
    const int u2 = tid & 63,  bg2 = tid >> 6;

    const float4* __restrict__ U1p4  = (const float4*)g_U1p;   // [k*128 + u1]
    const float4* __restrict__ WU2p4 = (const float4*)g_WU2p;  // [k*64  + u2]

    const float4 w1q = make_float4(W1[u1], W1[128 + u1], W1[256 + u1], W1[384 + u1]);
    const float4 b1q = make_float4(b1[u1], b1[128 + u1], b1[256 + u1], b1[384 + u1]);
    const float4 b2q = make_float4(b2[u2], b2[64 + u2], b2[128 + u2], b2[192 + u2]);

    float c1[8], c2[4];
#pragma unroll
    for (int j = 0; j < 8; j++) c1[j] = 0.0f;
#pragma unroll
    for (int j = 0; j < 4; j++) c2[j] = 0.0f;

    __syncthreads();

    for (int t = 0; t < T_SEQ; t++) {
        // ---- layer 1: z1 = x_t*W1 + h1 @ U1 + b1 ----
        float ai[8], af[8], ag[8], ao[8];
#pragma unroll
        for (int j = 0; j < 8; j++) {
            float xv = xs[t * BT + bg1 * 8 + j];
            ai[j] = fmaf(xv, w1q.x, b1q.x);
            af[j] = fmaf(xv, w1q.y, b1q.y);
            ag[j] = fmaf(xv, w1q.z, b1q.z);
            ao[j] = fmaf(xv, w1q.w, b1q.w);
        }
        const float* hp = hcat + bg1 * 8;
#pragma unroll 4
        for (int k = 0; k < 128; k++) {
            float4 w  = U1p4[k * 128 + u1];
            float4 hA = *(const float4*)(hp + k * HROW);
            float4 hB = *(const float4*)(hp + k * HROW + 4);
            float hv[8] = {hA.x, hA.y, hA.z, hA.w, hB.x, hB.y, hB.z, hB.w};
#pragma unroll
            for (int j = 0; j < 8; j++) {
                ai[j] = fmaf(hv[j], w.x, ai[j]);
                af[j] = fmaf(hv[j], w.y, af[j]);
                ag[j] = fmaf(hv[j], w.z, ag[j]);
                ao[j] = fmaf(hv[j], w.w, ao[j]);
            }
        }
        __syncthreads();  // all reads of old h1 complete
#pragma unroll
        for (int j = 0; j < 8; j++) {
            float iv = sigmoidf_(ai[j]);
            float fv = sigmoidf_(af[j]);
            float gv = fmaxf(ag[j], 0.0f);
            float ov = sigmoidf_(ao[j]);
            float c  = fmaf(fv, c1[j], iv * gv);
            c1[j] = c;
            hcat[u1 * HROW + bg1 * 8 + j] = ov * fmaxf(c, 0.0f);
        }
        __syncthreads();  // new h1 visible

        // ---- layer 2: z2 = h1_t @ W2 + h2 @ U2 + b2 (single K=192 loop) ----
        float a2i[4], a2f[4], a2g[4], a2o[4];
#pragma unroll
        for (int j = 0; j < 4; j++) {
            a2i[j] = b2q.x; a2f[j] = b2q.y; a2g[j] = b2q.z; a2o[j] = b2q.w;
        }
        const float* hp2 = hcat + bg2 * 4;
#pragma unroll 4
        for (int k = 0; k < 192; k++) {
            float4 w = WU2p4[k * 64 + u2];
            float4 h = *(const float4*)(hp2 + k * HROW);
            float hv[4] = {h.x, h.y, h.z, h.w};
#pragma unroll
            for (int j = 0; j < 4; j++) {
                a2i[j] = fmaf(hv[j], w.x, a2i[j]);
                a2f[j] = fmaf(hv[j], w.y, a2f[j]);
                a2g[j] = fmaf(hv[j], w.z, a2g[j]);
                a2o[j] = fmaf(hv[j], w.w, a2o[j]);
            }
        }
        __syncthreads();  // all reads of old h2 complete
#pragma unroll
        for (int j = 0; j < 4; j++) {
            float iv = sigmoidf_(a2i[j]);
            float fv = sigmoidf_(a2f[j]);
            float gv = fmaxf(a2g[j], 0.0f);
            float ov = sigmoidf_(a2o[j]);
            float c  = fmaf(fv, c2[j], iv * gv);
            c2[j] = c;
            float h = ov * fmaxf(c, 0.0f);
            hcat[(128 + u2) * HROW + bg2 * 4 + j] = h;
            if (t == T_SEQ - 1) g_h2last[(b0 + bg2 * 4 + j) * 64 + u2] = h;
        }
        // next-iteration layer-1 pass only touches rows <128; the two barriers
        // above separate this write from the next read of rows >=128.
    }
}

// ---------------------------------------------------------------------------
// Phase B: RepeatVector(h2_last) -> LSTM3 (H=64) -> LSTM4 (H=128) -> Dense(1).
// hcat rows 0..63 = h3, rows 64..191 = h4.
// Layer-3 input path (h2_last @ W3 + b3) is constant over t -> held in regs.
// ---------------------------------------------------------------------------
__global__ void __launch_bounds__(256, 1)
phaseB_kernel(const float* __restrict__ b3, const float* __restrict__ b4,
              const float* __restrict__ Wd, const float* __restrict__ bd,
              float* __restrict__ out) {
    __shared__ float hcat[192 * HROW];
    __shared__ float h2T[64 * BT];  // [k][b]

    const int tid = threadIdx.x;
    const int b0 = blockIdx.x * BT;

    for (int i = tid; i < 64 * BT; i += 256) {
        int b = i >> 6, k = i & 63;
        h2T[k * BT + b] = g_h2last[(b0 + b) * 64 + k];
    }
    for (int i = tid; i < 192 * HROW; i += 256) hcat[i] = 0.0f;

    const int u3 = tid & 63,  bg  = tid >> 6;  // 4 samples
    const int u4 = tid & 127, bg2 = tid >> 7;  // 8 samples
    const int lane16 = tid & 15, bq = tid >> 4;

    const float4* __restrict__ W3p4  = (const float4*)g_W3p;
    const float4* __restrict__ U3p4  = (const float4*)g_U3p;
    const float4* __restrict__ WU4p4 = (const float4*)g_WU4p;

    const float4 b4q = make_float4(b4[u4], b4[128 + u4], b4[256 + u4], b4[384 + u4]);
    float wd[8];
#pragma unroll
    for (int r = 0; r < 8; r++) wd[r] = Wd[lane16 + 16 * r];
    const float bdv = bd[0];

    __syncthreads();

    // precompute zx3 = h2_last @ W3 + b3 (constant over t) into registers
    float zi[4], zf[4], zg[4], zo[4];
    {
        const float4 b3q = make_float4(b3[u3], b3[64 + u3], b3[128 + u3], b3[192 + u3]);
#pragma unroll
        for (int j = 0; j < 4; j++) { zi[j] = b3q.x; zf[j] = b3q.y; zg[j] = b3q.z; zo[j] = b3q.w; }
#pragma unroll 4
        for (int k = 0; k < 64; k++) {
            float4 w = W3p4[k * 64 + u3];
            float4 h = *(const float4*)(h2T + k * BT + bg * 4);
            float hv[4] = {h.x, h.y, h.z, h.w};
#pragma unroll
            for (int j = 0; j < 4; j++) {
                zi[j] = fmaf(hv[j], w.x, zi[j]);
                zf[j] = fmaf(hv[j], w.y, zf[j]);
                zg[j] = fmaf(hv[j], w.z, zg[j]);
                zo[j] = fmaf(hv[j], w.w, zo[j]);
            }
        }
    }

    float c3[4], c4[8];
#pragma unroll
    for (int j = 0; j < 4; j++) c3[j] = 0.0f;
#pragma unroll
    for (int j = 0; j < 8; j++) c4[j] = 0.0f;

    for (int t = 0; t < T_SEQ; t++) {
        // ---- layer 3: z3 = zx3 + h3 @ U3 ----
        float a3i[4], a3f[4], a3g[4], a3o[4];
#pragma unroll
        for (int j = 0; j < 4; j++) { a3i[j] = zi[j]; a3f[j] = zf[j]; a3g[j] = zg[j]; a3o[j] = zo[j]; }
        const float* hp3 = hcat + bg * 4;
#pragma unroll 4
        for (int k = 0; k < 64; k++) {
            float4 w = U3p4[k * 64 + u3];
            float4 h = *(const float4*)(hp3 + k * HROW);
            float hv[4] = {h.x, h.y, h.z, h.w};
#pragma unroll
            for (int j = 0; j < 4; j++) {
                a3i[j] = fmaf(hv[j], w.x, a3i[j]);
                a3f[j] = fmaf(hv[j], w.y, a3f[j]);
                a3g[j] = fmaf(hv[j], w.z, a3g[j]);
                a3o[j] = fmaf(hv[j], w.w, a3o[j]);
            }
        }
        __syncthreads();
#pragma unroll
        for (int j = 0; j < 4; j++) {
            float iv = sigmoidf_(a3i[j]);
            float fv = sigmoidf_(a3f[j]);
            float gv = fmaxf(a3g[j], 0.0f);
            float ov = sigmoidf_(a3o[j]);
            float c  = fmaf(fv, c3[j], iv * gv);
            c3[j] = c;
            hcat[u3 * HROW + bg * 4 + j] = ov * fmaxf(c, 0.0f);
        }
        __syncthreads();

        // ---- layer 4: z4 = h3_t @ W4 + h4 @ U4 + b4 (K=192) ----
        float a4i[8], a4f[8], a4g[8], a4o[8];
#pragma unroll
        for (int j = 0; j < 8; j++) { a4i[j] = b4q.x; a4f[j] = b4q.y; a4g[j] = b4q.z; a4o[j] = b4q.w; }
        const float* hp4 = hcat + bg2 * 8;
#pragma unroll 4
        for (int k = 0; k < 192; k++) {
            float4 w  = WU4p4[k * 128 + u4];
            float4 hA = *(const float4*)(hp4 + k * HROW);
            float4 hB = *(const float4*)(hp4 + k * HROW + 4);
            float hv[8] = {hA.x, hA.y, hA.z, hA.w, hB.x, hB.y, hB.z, hB.w};
#pragma unroll
            for (int j = 0; j < 8; j++) {
                a4i[j] = fmaf(hv[j], w.x, a4i[j]);
                a4f[j] = fmaf(hv[j], w.y, a4f[j]);
                a4g[j] = fmaf(hv[j], w.z, a4g[j]);
                a4o[j] = fmaf(hv[j], w.w, a4o[j]);
            }
        }
        __syncthreads();
#pragma unroll
        for (int j = 0; j < 8; j++) {
            float iv = sigmoidf_(a4i[j]);
            float fv = sigmoidf_(a4f[j]);
            float gv = fmaxf(a4g[j], 0.0f);
            float ov = sigmoidf_(a4o[j]);
            float c  = fmaf(fv, c4[j], iv * gv);
            c4[j] = c;
            hcat[(64 + u4) * HROW + bg2 * 8 + j] = ov * fmaxf(c, 0.0f);
        }
        __syncthreads();

        // ---- dense: out[b][t] = h4 . Wd + bd (16-lane tree per sample) ----
        float s = 0.0f;
#pragma unroll
        for (int r = 0; r < 8; r++)
            s = fmaf(hcat[(64 + lane16 + 16 * r) * HROW + bq], wd[r], s);
        s += __shfl_xor_sync(0xffffffffu, s, 8);
        s += __shfl_xor_sync(0xffffffffu, s, 4);
        s += __shfl_xor_sync(0xffffffffu, s, 2);
        s += __shfl_xor_sync(0xffffffffu, s, 1);
        if (lane16 == 0) out[(b0 + bq) * T_SEQ + t] = s + bdv;
        // dense reads complete before bar1 of the next iteration; h4 rows are
        // rewritten only after three more barriers.
    }
}

// ---------------------------------------------------------------------------
extern "C" void kernel_launch(void* const* d_in, const int* in_sizes, int n_in,
                              void* d_out, int out_size) {
    const float* x  = (const float*)d_in[0];
    const float* W1 = (const float*)d_in[1];
    const float* U1 = (const float*)d_in[2];
    const float* b1 = (const float*)d_in[3];
    const float* W2 = (const float*)d_in[4];
    const float* U2 = (const float*)d_in[5];
    const float* b2 = (const float*)d_in[6];
    const float* W3 = (const float*)d_in[7];
    const float* U3 = (const float*)d_in[8];
    const float* b3 = (const float*)d_in[9];
    const float* W4 = (const float*)d_in[10];
    const float* U4 = (const float*)d_in[11];
    const float* b4 = (const float*)d_in[12];
    const float* Wd = (const float*)d_in[13];
    const float* bd = (const float*)d_in[14];
    float* out = (float*)d_out;

    pack_kernel<<<960, 256>>>(U1, W2, U2, W3, U3, W4, U4);
    phaseA_kernel<<<NBLK, 256>>>(x, W1, b1, b2);
    phaseB_kernel<<<NBLK, 256>>>(b3, b4, Wd, bd, out);
}